// round 1
// baseline (speedup 1.0000x reference)
#include <cuda_runtime.h>
#include <cuda_bf16.h>
#include <math.h>

// ---------------------------------------------------------------------------
// GNN_11957188952096: pre-linear -> SAGE(32->64) -> SAGE(64->64) -> pool -> MLP
// N=100000 nodes, E=1600000 edges, G=512 graphs
// ---------------------------------------------------------------------------

#define MAXN 100000
#define MAXG 512

// scratch (static device globals -- allocation-free)
__device__ float g_h0[MAXN * 32];     // pre-linear output
__device__ float g_h1[MAXN * 64];     // conv1 output
__device__ float g_agg32[MAXN * 32];  // conv1 neighbor sums
__device__ float g_agg64[MAXN * 64];  // conv2 neighbor sums
__device__ float g_cnt[MAXN];         // in-degree (shared by both convs)
__device__ float g_gsum[MAXG * 64];   // pooled sums
__device__ float g_gcnt[MAXG];        // nodes per graph

// ---------------------------------------------------------------------------
__global__ void zero_all(int N) {
    int i = blockIdx.x * blockDim.x + threadIdx.x;
    int stride = gridDim.x * blockDim.x;
    for (int k = i; k < N * 32; k += stride) g_agg32[k] = 0.f;
    for (int k = i; k < N * 64; k += stride) g_agg64[k] = 0.f;
    for (int k = i; k < N; k += stride) g_cnt[k] = 0.f;
    for (int k = i; k < MAXG * 64; k += stride) g_gsum[k] = 0.f;
    for (int k = i; k < MAXG; k += stride) g_gcnt[k] = 0.f;
}

// h0 = relu(x @ pre_w + pre_b)   x:[N,5]  pre_w:[5,32]
__global__ void pre_kernel(const float* __restrict__ x,
                           const float* __restrict__ w,
                           const float* __restrict__ b, int N) {
    __shared__ float sw[5 * 32];
    __shared__ float sb[32];
    for (int i = threadIdx.x; i < 160; i += blockDim.x) sw[i] = w[i];
    if (threadIdx.x < 32) sb[threadIdx.x] = b[threadIdx.x];
    __syncthreads();
    int n = blockIdx.x * blockDim.x + threadIdx.x;
    if (n >= N) return;
    float xv[5];
#pragma unroll
    for (int k = 0; k < 5; k++) xv[k] = x[n * 5 + k];
#pragma unroll
    for (int j = 0; j < 32; j++) {
        float acc = sb[j];
#pragma unroll
        for (int k = 0; k < 5; k++) acc = fmaf(xv[k], sw[k * 32 + j], acc);
        g_h0[n * 32 + j] = fmaxf(acc, 0.f);
    }
}

// in-degree counts (used by both convs)
__global__ void count_kernel(const int* __restrict__ dst, int E) {
    int e = blockIdx.x * blockDim.x + threadIdx.x;
    if (e < E) atomicAdd(&g_cnt[dst[e]], 1.f);
}

// scatter conv1: agg32[dst] += h0[src]   (8 threads per edge, float4 each)
__global__ void scatter32(const int* __restrict__ src, const int* __restrict__ dst,
                          long long total) {
    long long idx = (long long)blockIdx.x * blockDim.x + threadIdx.x;
    if (idx >= total) return;
    int e = (int)(idx >> 3);
    int q = (int)(idx & 7);
    int s = src[e];
    int d = dst[e];
    float4 v = reinterpret_cast<const float4*>(g_h0)[s * 8 + q];
    float* base = &g_agg32[d * 32 + q * 4];
    atomicAdd(base + 0, v.x);
    atomicAdd(base + 1, v.y);
    atomicAdd(base + 2, v.z);
    atomicAdd(base + 3, v.w);
}

// conv1 combine: h1 = relu(l2norm(mean_agg @ Wl + bl + h0 @ Wr))
// warp per node; lane holds input-dim "lane"; lane computes out dims lane, lane+32
__global__ void combine1(const float* __restrict__ wl, const float* __restrict__ bl,
                         const float* __restrict__ wr, int N) {
    __shared__ float swl[32 * 64];
    __shared__ float swr[32 * 64];
    __shared__ float sbl[64];
    for (int i = threadIdx.x; i < 32 * 64; i += blockDim.x) {
        swl[i] = wl[i];
        swr[i] = wr[i];
    }
    if (threadIdx.x < 64) sbl[threadIdx.x] = bl[threadIdx.x];
    __syncthreads();

    int n = (blockIdx.x * blockDim.x + threadIdx.x) >> 5;
    int lane = threadIdx.x & 31;
    if (n >= N) return;

    float c = g_cnt[n];
    float inv_c = c > 0.f ? 1.f / c : 0.f;
    float aggv = g_agg32[n * 32 + lane] * inv_c;
    float hv = g_h0[n * 32 + lane];

    float acc0 = sbl[lane];
    float acc1 = sbl[lane + 32];
#pragma unroll
    for (int l = 0; l < 32; l++) {
        float a = __shfl_sync(0xffffffffu, aggv, l);
        float h = __shfl_sync(0xffffffffu, hv, l);
        acc0 = fmaf(a, swl[l * 64 + lane], acc0);
        acc0 = fmaf(h, swr[l * 64 + lane], acc0);
        acc1 = fmaf(a, swl[l * 64 + lane + 32], acc1);
        acc1 = fmaf(h, swr[l * 64 + lane + 32], acc1);
    }
    float ss = acc0 * acc0 + acc1 * acc1;
#pragma unroll
    for (int o = 16; o > 0; o >>= 1) ss += __shfl_xor_sync(0xffffffffu, ss, o);
    float inv = 1.f / fmaxf(sqrtf(ss), 1e-12f);
    g_h1[n * 64 + lane] = fmaxf(acc0 * inv, 0.f);
    g_h1[n * 64 + lane + 32] = fmaxf(acc1 * inv, 0.f);
}

// scatter conv2: agg64[dst] += h1[src]   (16 threads per edge, float4 each)
__global__ void scatter64(const int* __restrict__ src, const int* __restrict__ dst,
                          long long total) {
    long long idx = (long long)blockIdx.x * blockDim.x + threadIdx.x;
    if (idx >= total) return;
    int e = (int)(idx >> 4);
    int q = (int)(idx & 15);
    int s = src[e];
    int d = dst[e];
    float4 v = reinterpret_cast<const float4*>(g_h1)[s * 16 + q];
    float* base = &g_agg64[d * 64 + q * 4];
    atomicAdd(base + 0, v.x);
    atomicAdd(base + 1, v.y);
    atomicAdd(base + 2, v.z);
    atomicAdd(base + 3, v.w);
}

// conv2 combine + global pooling (h2 never stored)
__global__ void combine2_pool(const int* __restrict__ batch,
                              const float* __restrict__ wl, const float* __restrict__ bl,
                              const float* __restrict__ wr, int N) {
    __shared__ float swl[64 * 64];
    __shared__ float swr[64 * 64];
    __shared__ float sbl[64];
    for (int i = threadIdx.x; i < 64 * 64; i += blockDim.x) {
        swl[i] = wl[i];
        swr[i] = wr[i];
    }
    if (threadIdx.x < 64) sbl[threadIdx.x] = bl[threadIdx.x];
    __syncthreads();

    int n = (blockIdx.x * blockDim.x + threadIdx.x) >> 5;
    int lane = threadIdx.x & 31;
    if (n >= N) return;

    float c = g_cnt[n];
    float inv_c = c > 0.f ? 1.f / c : 0.f;
    float a0 = g_agg64[n * 64 + lane] * inv_c;
    float a1 = g_agg64[n * 64 + 32 + lane] * inv_c;
    float h0 = g_h1[n * 64 + lane];
    float h1 = g_h1[n * 64 + 32 + lane];

    float acc0 = sbl[lane];
    float acc1 = sbl[lane + 32];
#pragma unroll
    for (int l = 0; l < 32; l++) {
        float b0 = __shfl_sync(0xffffffffu, a0, l);
        float b1 = __shfl_sync(0xffffffffu, a1, l);
        float c0 = __shfl_sync(0xffffffffu, h0, l);
        float c1 = __shfl_sync(0xffffffffu, h1, l);
        acc0 = fmaf(b0, swl[l * 64 + lane], acc0);
        acc0 = fmaf(b1, swl[(l + 32) * 64 + lane], acc0);
        acc0 = fmaf(c0, swr[l * 64 + lane], acc0);
        acc0 = fmaf(c1, swr[(l + 32) * 64 + lane], acc0);
        acc1 = fmaf(b0, swl[l * 64 + lane + 32], acc1);
        acc1 = fmaf(b1, swl[(l + 32) * 64 + lane + 32], acc1);
        acc1 = fmaf(c0, swr[l * 64 + lane + 32], acc1);
        acc1 = fmaf(c1, swr[(l + 32) * 64 + lane + 32], acc1);
    }
    float ss = acc0 * acc0 + acc1 * acc1;
#pragma unroll
    for (int o = 16; o > 0; o >>= 1) ss += __shfl_xor_sync(0xffffffffu, ss, o);
    float inv = 1.f / fmaxf(sqrtf(ss), 1e-12f);
    float v0 = fmaxf(acc0 * inv, 0.f);
    float v1 = fmaxf(acc1 * inv, 0.f);

    int b = batch[n];
    atomicAdd(&g_gsum[b * 64 + lane], v0);
    atomicAdd(&g_gsum[b * 64 + 32 + lane], v1);
    if (lane == 0) atomicAdd(&g_gcnt[b], 1.f);
}

// head: g = gsum/max(gcnt,1); relu(g@p1+b); relu(.@p2+b); .@o + b
__global__ void head_kernel(const float* __restrict__ p1w, const float* __restrict__ p1b,
                            const float* __restrict__ p2w, const float* __restrict__ p2b,
                            const float* __restrict__ ow, const float* __restrict__ ob,
                            float* __restrict__ out) {
    int g = blockIdx.x;  // 512 blocks x 64 threads
    int t = threadIdx.x;
    __shared__ float sg[64];
    __shared__ float sh[64];
    __shared__ float s2[16];

    float c = g_gcnt[g];
    float invc = 1.f / fmaxf(c, 1.f);
    sg[t] = g_gsum[g * 64 + t] * invc;
    __syncthreads();

    float acc = p1b[t];
#pragma unroll 8
    for (int k = 0; k < 64; k++) acc = fmaf(sg[k], p1w[k * 64 + t], acc);
    sh[t] = fmaxf(acc, 0.f);
    __syncthreads();

    if (t < 16) {
        float a = p2b[t];
#pragma unroll 8
        for (int k = 0; k < 64; k++) a = fmaf(sh[k], p2w[k * 16 + t], a);
        s2[t] = fmaxf(a, 0.f);
    }
    __syncthreads();

    if (t == 0) {
        float a = ob[0];
#pragma unroll
        for (int k = 0; k < 16; k++) a = fmaf(s2[k], ow[k], a);
        out[g] = a;
    }
}

// ---------------------------------------------------------------------------
extern "C" void kernel_launch(void* const* d_in, const int* in_sizes, int n_in,
                              void* d_out, int out_size) {
    const float* x = (const float*)d_in[0];
    const int* ei = (const int*)d_in[1];
    const int* batch = (const int*)d_in[2];

    // weights are the last 14 inputs (robust to whether num_graphs scalar is passed)
    int base = n_in - 14;
    const float* pre_w = (const float*)d_in[base + 0];
    const float* pre_b = (const float*)d_in[base + 1];
    const float* c1_wl = (const float*)d_in[base + 2];
    const float* c1_bl = (const float*)d_in[base + 3];
    const float* c1_wr = (const float*)d_in[base + 4];
    const float* c2_wl = (const float*)d_in[base + 5];
    const float* c2_bl = (const float*)d_in[base + 6];
    const float* c2_wr = (const float*)d_in[base + 7];
    const float* p1_w = (const float*)d_in[base + 8];
    const float* p1_b = (const float*)d_in[base + 9];
    const float* p2_w = (const float*)d_in[base + 10];
    const float* p2_b = (const float*)d_in[base + 11];
    const float* o_w = (const float*)d_in[base + 12];
    const float* o_b = (const float*)d_in[base + 13];

    int N = in_sizes[0] / 5;
    int E = in_sizes[1] / 2;
    const int* src = ei;
    const int* dst = ei + E;
    float* out = (float*)d_out;

    // 1. zero scratch
    zero_all<<<2048, 256>>>(N);

    // 2. pre-linear
    pre_kernel<<<(N + 255) / 256, 256>>>(x, pre_w, pre_b, N);

    // 3. degree counts
    count_kernel<<<(E + 255) / 256, 256>>>(dst, E);

    // 4. conv1 scatter (E*8 threads)
    {
        long long total = (long long)E * 8;
        int blocks = (int)((total + 255) / 256);
        scatter32<<<blocks, 256>>>(src, dst, total);
    }

    // 5. conv1 combine (warp per node)
    combine1<<<(N * 32 + 255) / 256, 256>>>(c1_wl, c1_bl, c1_wr, N);

    // 6. conv2 scatter (E*16 threads)
    {
        long long total = (long long)E * 16;
        int blocks = (int)((total + 255) / 256);
        scatter64<<<blocks, 256>>>(src, dst, total);
    }

    // 7. conv2 combine + pool (warp per node)
    combine2_pool<<<(N * 32 + 255) / 256, 256>>>(batch, c2_wl, c2_bl, c2_wr, N);

    // 8. head
    head_kernel<<<out_size, 64>>>(p1_w, p1_b, p2_w, p2_b, o_w, o_b, out);
}